// round 6
// baseline (speedup 1.0000x reference)
#include <cuda_runtime.h>

#define P 576
#define NC 3
#define KDIM 4
#define THREADS 576
#define GRID 592

__device__ float g_sum[P];      // zero at load; reset by last block each run
__device__ float g_sumsq[P];
__device__ unsigned int g_ticket;  // zero at load; reset by last block

__global__ __launch_bounds__(THREADS, 3) void csoap_fused_kernel(
    const float* __restrict__ X,
    const float* __restrict__ mu,
    const float* __restrict__ W,
    float* __restrict__ out,
    int n_rows, int rows_per_block, float inv_n)
{
    const int col = threadIdx.x;

    int r0 = blockIdx.x * rows_per_block;
    int r1 = r0 + rows_per_block;
    if (r1 > n_rows) r1 = n_rows;

    // ---- per-column accumulation: thread owns one column, coalesced LDG.32,
    //      8-way unroll for deep MLP (8 independent loads in flight) ----
    float s = 0.0f, s2 = 0.0f;
    if (r0 < r1) {
        const float* p = X + (size_t)r0 * P + col;
        int r = r0;
        for (; r + 8 <= r1; r += 8) {
            float a0 = p[0 * P];
            float a1 = p[1 * P];
            float a2 = p[2 * P];
            float a3 = p[3 * P];
            float a4 = p[4 * P];
            float a5 = p[5 * P];
            float a6 = p[6 * P];
            float a7 = p[7 * P];
            p += 8 * P;
            s  += ((a0 + a1) + (a2 + a3)) + ((a4 + a5) + (a6 + a7));
            s2 += ((a0 * a0 + a1 * a1) + (a2 * a2 + a3 * a3))
                + ((a4 * a4 + a5 * a5) + (a6 * a6 + a7 * a7));
        }
        for (; r < r1; r++) {
            float a = p[0];
            p += P;
            s  += a;
            s2 += a * a;
        }
        atomicAdd(&g_sum[col],   s);
        atomicAdd(&g_sumsq[col], s2);
    }

    // ---- last-block election ----
    __threadfence();
    __syncthreads();
    __shared__ int is_last;
    if (threadIdx.x == 0)
        is_last = (atomicAdd(&g_ticket, 1u) == (unsigned)(gridDim.x - 1));
    __syncthreads();

    if (!is_last) return;

    // ---- finalize + project (576 threads, one per feature column) ----
    __shared__ float s_acc[KDIM];
    const int j = threadIdx.x;
    if (j < KDIM) s_acc[j] = 0.0f;
    __syncthreads();

    float total   = __ldcg(&g_sum[j]);     // L2 read, bypass L1
    float totalsq = __ldcg(&g_sumsq[j]);
    float m    = total * inv_n;
    float mom2 = fmaf(-m, m, totalsq * inv_n);   // E[x^2] - m^2

    // reset scratch for the next graph replay
    g_sum[j]   = 0.0f;
    g_sumsq[j] = 0.0f;
    if (j == 0) g_ticket = 0u;

    int jb = j * NC;
    float d0 = m    - mu[jb + 0];
    float d1 = 0.0f - mu[jb + 1];
    float d2 = mom2 - mu[jb + 2];

    float acc[KDIM];
    #pragma unroll
    for (int k = 0; k < KDIM; k++) {
        acc[k] = d0 * W[(jb + 0) * KDIM + k]
               + d1 * W[(jb + 1) * KDIM + k]
               + d2 * W[(jb + 2) * KDIM + k];
    }

    #pragma unroll
    for (int k = 0; k < KDIM; k++) {
        float v = acc[k];
        #pragma unroll
        for (int off = 16; off > 0; off >>= 1)
            v += __shfl_down_sync(0xFFFFFFFFu, v, off);
        if ((threadIdx.x & 31) == 0)
            atomicAdd(&s_acc[k], v);
    }
    __syncthreads();

    if (j < KDIM) out[j] = s_acc[j];
}

extern "C" void kernel_launch(void* const* d_in, const int* in_sizes, int n_in,
                              void* d_out, int out_size)
{
    const float* X  = (const float*)d_in[0];
    const float* mu = (const float*)d_in[1];
    const float* W  = (const float*)d_in[2];
    float* out = (float*)d_out;

    int n_rows = in_sizes[0] / P;
    int rows_per_block = (n_rows + GRID - 1) / GRID;

    csoap_fused_kernel<<<GRID, THREADS>>>(X, mu, W, out, n_rows,
                                          rows_per_block, 1.0f / (float)n_rows);
}